// round 3
// baseline (speedup 1.0000x reference)
#include <cuda_runtime.h>
#include <cuda_bf16.h>
#include <math.h>

#define VOCAB 50000
#define D 256
#define Bn 128
#define Sn 64
#define Ln 32
#define Kn 32

// Scratch (device globals: allocation-free rule)
__device__ float g_enc [Bn * Sn * D];   // enc_sents  (B,S,D)  8 MB
__device__ float g_encW[Bn * Sn * D];   // enc_sents@W (B,S,D) 8 MB
__device__ float g_keysV[Bn * Kn * D];  // keys@V     (B,K,D)  4 MB

// ---------------------------------------------------------------------------
// Kernel 1: enc_sents[b,s,d] = sum_l emb[prgrph[b,s,l], d]
// grid = B*S blocks, 256 threads (t = d)
// ---------------------------------------------------------------------------
__global__ void gather_kernel(const int* __restrict__ prgrph,
                              const float* __restrict__ emb) {
    __shared__ int sidx[Ln];
    int bs = blockIdx.x;
    int t  = threadIdx.x;
    if (t < Ln) sidx[t] = prgrph[(size_t)bs * Ln + t];
    __syncthreads();
    float acc = 0.f;
#pragma unroll
    for (int l = 0; l < Ln; ++l) {
        acc += __ldg(emb + (size_t)sidx[l] * D + t);
    }
    g_enc[(size_t)bs * D + t] = acc;
}

// ---------------------------------------------------------------------------
// Generic 32-row GEMM tile: C[32,D] = A[32,D] @ Bm[D,D]  (row-major, D=256)
// block = 256 threads, thread t owns output column t, acc over 32 rows.
// ---------------------------------------------------------------------------
__device__ __forceinline__ void gemm32_body(const float* __restrict__ Ab,
                                            const float* __restrict__ Bm,
                                            float* __restrict__ Cb) {
    __shared__ float a_sh[32 * D];
    int t = threadIdx.x;
    for (int i = t; i < 32 * D; i += 256) a_sh[i] = Ab[i];
    __syncthreads();

    float acc[32];
#pragma unroll
    for (int k = 0; k < 32; ++k) acc[k] = 0.f;

    for (int d0 = 0; d0 < D; d0 += 8) {
        float u[8];
#pragma unroll
        for (int i = 0; i < 8; ++i) u[i] = __ldg(Bm + (size_t)(d0 + i) * D + t);
#pragma unroll
        for (int k = 0; k < 32; ++k) {
            float4 h1 = *(const float4*)&a_sh[k * D + d0];
            float4 h2 = *(const float4*)&a_sh[k * D + d0 + 4];
            acc[k] = fmaf(h1.x, u[0], acc[k]); acc[k] = fmaf(h1.y, u[1], acc[k]);
            acc[k] = fmaf(h1.z, u[2], acc[k]); acc[k] = fmaf(h1.w, u[3], acc[k]);
            acc[k] = fmaf(h2.x, u[4], acc[k]); acc[k] = fmaf(h2.y, u[5], acc[k]);
            acc[k] = fmaf(h2.z, u[6], acc[k]); acc[k] = fmaf(h2.w, u[7], acc[k]);
        }
    }
#pragma unroll
    for (int k = 0; k < 32; ++k) Cb[k * D + t] = acc[k];
}

// encW = g_enc @ W   : grid = (B*S)/32 = 256 blocks
__global__ void gemm_encW_kernel(const float* __restrict__ W) {
    size_t off = (size_t)blockIdx.x * 32 * D;
    gemm32_body(g_enc + off, W, g_encW + off);
}

// keysV = keys @ V   : grid = (B*K)/32 = 128 blocks
__global__ void gemm_keysV_kernel(const float* __restrict__ keys,
                                  const float* __restrict__ V) {
    size_t off = (size_t)blockIdx.x * 32 * D;
    gemm32_body(keys + off, V, g_keysV + off);
}

// ---------------------------------------------------------------------------
// Kernel 2: the scan. One CTA per batch b; h lives in shared memory.
// 256 threads: thread t = column t; warp w handles rows 4w..4w+3 in reductions.
// ---------------------------------------------------------------------------
__global__ void __launch_bounds__(256, 1)
scan_kernel(const float* __restrict__ keys,
            const int* __restrict__ pmask,   // bool materialized as int32 (B,S,L)
            const float* __restrict__ U,
            float* __restrict__ out) {
    extern __shared__ float sm[];
    float* h       = sm;                 // K*D
    float* ks      = h  + Kn * D;        // K*D
    float* kv      = ks + Kn * D;        // K*D
    float* e_sh    = kv + Kn * D;        // D
    float* ew_sh   = e_sh + D;           // D
    float* gate_sh = ew_sh + D;          // K
    float* rs_sh   = gate_sh + Kn;       // K

    const int b    = blockIdx.x;
    const int t    = threadIdx.x;
    const int w    = t >> 5;
    const int lane = t & 31;

    for (int i = t; i < Kn * D; i += 256) {
        h[i]  = 0.f;
        ks[i] = keys[(size_t)b * Kn * D + i];
        kv[i] = g_keysV[(size_t)b * Kn * D + i];
    }
    __syncthreads();

    for (int s = 0; s < Sn; ++s) {
        // sent_mask[b,s] = prgrph_mask[b,s,0]; uniform branch across block
        if (pmask[((size_t)b * Sn + s) * Ln] == 0) continue;

        e_sh[t]  = g_enc [((size_t)b * Sn + s) * D + t];
        ew_sh[t] = g_encW[((size_t)b * Sn + s) * D + t];
        __syncthreads();

        // gate[k] = sigmoid( sum_d e[d] * (h[k,d] + keys[k,d]) )
#pragma unroll
        for (int r = 0; r < 4; ++r) {
            int k = w * 4 + r;
            float p = 0.f;
#pragma unroll
            for (int j = 0; j < 8; ++j) {
                int c = lane + 32 * j;
                p = fmaf(e_sh[c], h[k * D + c] + ks[k * D + c], p);
            }
#pragma unroll
            for (int o = 16; o > 0; o >>= 1) p += __shfl_xor_sync(0xffffffffu, p, o);
            if (lane == 0) gate_sh[k] = 1.f / (1.f + expf(-p));
        }
        __syncthreads();

        // acc[k] = (h @ U)[k, t]
        float acc[Kn];
#pragma unroll
        for (int k = 0; k < Kn; ++k) acc[k] = 0.f;
        for (int d0 = 0; d0 < D; d0 += 8) {
            float u[8];
#pragma unroll
            for (int i = 0; i < 8; ++i) u[i] = __ldg(U + (size_t)(d0 + i) * D + t);
#pragma unroll
            for (int k = 0; k < Kn; ++k) {
                float4 h1 = *(const float4*)&h[k * D + d0];
                float4 h2 = *(const float4*)&h[k * D + d0 + 4];
                acc[k] = fmaf(h1.x, u[0], acc[k]); acc[k] = fmaf(h1.y, u[1], acc[k]);
                acc[k] = fmaf(h1.z, u[2], acc[k]); acc[k] = fmaf(h1.w, u[3], acc[k]);
                acc[k] = fmaf(h2.x, u[4], acc[k]); acc[k] = fmaf(h2.y, u[5], acc[k]);
                acc[k] = fmaf(h2.z, u[6], acc[k]); acc[k] = fmaf(h2.w, u[7], acc[k]);
            }
        }

        // upd[k,t] = h[k,t] + gate[k] * relu(hU + keysV + eW)
        float ew = ew_sh[t];
#pragma unroll
        for (int k = 0; k < Kn; ++k) {
            float ht = fmaxf(acc[k] + kv[k * D + t] + ew, 0.f);
            acc[k] = fmaf(gate_sh[k], ht, h[k * D + t]);
        }
        __syncthreads();            // all GEMM/gate reads of old h are done
#pragma unroll
        for (int k = 0; k < Kn; ++k) h[k * D + t] = acc[k];
        __syncthreads();

        // row norms: rs[k] = rsqrt(max(sum_d upd^2, eps))
#pragma unroll
        for (int r = 0; r < 4; ++r) {
            int k = w * 4 + r;
            float p = 0.f;
#pragma unroll
            for (int j = 0; j < 8; ++j) {
                float v = h[k * D + lane + 32 * j];
                p = fmaf(v, v, p);
            }
#pragma unroll
            for (int o = 16; o > 0; o >>= 1) p += __shfl_xor_sync(0xffffffffu, p, o);
            if (lane == 0) rs_sh[k] = rsqrtf(fmaxf(p, 1e-12f));
        }
        __syncthreads();
#pragma unroll
        for (int k = 0; k < Kn; ++k) h[k * D + t] *= rs_sh[k];
        __syncthreads();
    }

    for (int i = t; i < Kn * D; i += 256) out[(size_t)b * Kn * D + i] = h[i];
}

// ---------------------------------------------------------------------------
extern "C" void kernel_launch(void* const* d_in, const int* in_sizes, int n_in,
                              void* d_out, int out_size) {
    const int*   prgrph = (const int*)d_in[0];
    const int*   pmask  = (const int*)d_in[1];   // bool -> int32 per harness dtype set
    const float* keys   = (const float*)d_in[2];
    const float* emb    = (const float*)d_in[3];
    const float* U      = (const float*)d_in[4];
    const float* V      = (const float*)d_in[5];
    const float* W      = (const float*)d_in[6];
    float*       out    = (float*)d_out;

    const int scan_smem = (3 * Kn * D + 2 * D + 2 * Kn) * (int)sizeof(float); // ~100.6 KB
    cudaFuncSetAttribute(scan_kernel, cudaFuncAttributeMaxDynamicSharedMemorySize,
                         scan_smem);

    gather_kernel<<<Bn * Sn, 256>>>(prgrph, emb);
    gemm_encW_kernel<<<(Bn * Sn) / 32, 256>>>(W);
    gemm_keysV_kernel<<<(Bn * Kn) / 32, 256>>>(keys, V);
    scan_kernel<<<Bn, 256, scan_smem>>>(keys, pmask, U, out);
}

// round 4
// speedup vs baseline: 1.7264x; 1.7264x over previous
#include <cuda_runtime.h>
#include <cuda_bf16.h>
#include <math.h>

#define VOCAB 50000
#define D 256
#define Bn 128
#define Sn 64
#define Ln 32
#define Kn 32

// Scratch (device globals: allocation-free rule)
__device__ float  g_enc [Bn * Sn * D];          // enc_sents   (B,S,D)
__device__ float  g_encW[Bn * Sn * D];          // enc_sents@W (B,S,D)
__device__ float  g_keysV[Bn * Kn * D];         // keys@V      (B,K,D)
__device__ float  g_eK  [Bn * Sn * Kn];         // enc·keys    (B,S,K)
__device__ float2 g_Upk [(D / 2) * D];          // U packed: [p][c] = (U[2p][c], U[2p+1][c])

#define FMA_F32X2(d_, a_, b_, c_) \
    asm("fma.rn.f32x2 %0, %1, %2, %3;" : "=l"(d_) : "l"(a_), "l"(b_), "l"(c_))

// ---------------------------------------------------------------------------
// enc_sents[b,s,d] = sum_l emb[prgrph[b,s,l], d]
// ---------------------------------------------------------------------------
__global__ void gather_kernel(const int* __restrict__ prgrph,
                              const float* __restrict__ emb) {
    __shared__ int sidx[Ln];
    int bs = blockIdx.x;
    int t  = threadIdx.x;
    if (t < Ln) sidx[t] = prgrph[(size_t)bs * Ln + t];
    __syncthreads();
    float acc = 0.f;
#pragma unroll
    for (int l = 0; l < Ln; ++l) acc += __ldg(emb + (size_t)sidx[l] * D + t);
    g_enc[(size_t)bs * D + t] = acc;
}

// ---------------------------------------------------------------------------
// Pack U rows into float2 pairs along d: g_Upk[p*D + c] = (U[2p][c], U[2p+1][c])
// ---------------------------------------------------------------------------
__global__ void packU_kernel(const float* __restrict__ U) {
    int p = blockIdx.x;        // 0..127
    int c = threadIdx.x;       // 0..255
    g_Upk[p * D + c] = make_float2(U[(2 * p) * D + c], U[(2 * p + 1) * D + c]);
}

// ---------------------------------------------------------------------------
// eK[b,s,k] = sum_d enc[b,s,d] * keys[b,k,d]       grid = B*S, 256 threads
// ---------------------------------------------------------------------------
__global__ void eK_kernel(const float* __restrict__ keys) {
    __shared__ float e_sh[D];
    int bs   = blockIdx.x;
    int b    = bs / Sn;
    int t    = threadIdx.x;
    int w    = t >> 5, lane = t & 31;
    e_sh[t]  = g_enc[(size_t)bs * D + t];
    __syncthreads();
#pragma unroll
    for (int r = 0; r < 4; ++r) {
        int k = w * 4 + r;
        const float* kr = keys + ((size_t)b * Kn + k) * D;
        float p = 0.f;
#pragma unroll
        for (int j = 0; j < 8; ++j) {
            int c = lane + 32 * j;
            p = fmaf(e_sh[c], __ldg(kr + c), p);
        }
#pragma unroll
        for (int o = 16; o > 0; o >>= 1) p += __shfl_xor_sync(0xffffffffu, p, o);
        if (lane == 0) g_eK[(size_t)bs * Kn + k] = p;
    }
}

// ---------------------------------------------------------------------------
// 32-row GEMM tile: C[32,D] = A[32,D] @ Bm[D,D]
// ---------------------------------------------------------------------------
__device__ __forceinline__ void gemm32_body(const float* __restrict__ Ab,
                                            const float* __restrict__ Bm,
                                            float* __restrict__ Cb) {
    __shared__ float a_sh[32 * D];
    int t = threadIdx.x;
    for (int i = t; i < 32 * D; i += 256) a_sh[i] = Ab[i];
    __syncthreads();

    float acc[32];
#pragma unroll
    for (int k = 0; k < 32; ++k) acc[k] = 0.f;

    for (int d0 = 0; d0 < D; d0 += 8) {
        float u[8];
#pragma unroll
        for (int i = 0; i < 8; ++i) u[i] = __ldg(Bm + (size_t)(d0 + i) * D + t);
#pragma unroll
        for (int k = 0; k < 32; ++k) {
            float4 h1 = *(const float4*)&a_sh[k * D + d0];
            float4 h2 = *(const float4*)&a_sh[k * D + d0 + 4];
            acc[k] = fmaf(h1.x, u[0], acc[k]); acc[k] = fmaf(h1.y, u[1], acc[k]);
            acc[k] = fmaf(h1.z, u[2], acc[k]); acc[k] = fmaf(h1.w, u[3], acc[k]);
            acc[k] = fmaf(h2.x, u[4], acc[k]); acc[k] = fmaf(h2.y, u[5], acc[k]);
            acc[k] = fmaf(h2.z, u[6], acc[k]); acc[k] = fmaf(h2.w, u[7], acc[k]);
        }
    }
#pragma unroll
    for (int k = 0; k < 32; ++k) Cb[k * D + t] = acc[k];
}

__global__ void gemm_encW_kernel(const float* __restrict__ W) {
    size_t off = (size_t)blockIdx.x * 32 * D;
    gemm32_body(g_enc + off, W, g_encW + off);
}
__global__ void gemm_keysV_kernel(const float* __restrict__ keys,
                                  const float* __restrict__ V) {
    size_t off = (size_t)blockIdx.x * 32 * D;
    gemm32_body(keys + off, V, g_keysV + off);
}

// ---------------------------------------------------------------------------
// The scan. One CTA per batch; 512 threads.
// Thread t: column c = t&255, k-half kh = t>>8 (rows kh*16 .. kh*16+15).
// ---------------------------------------------------------------------------
__global__ void __launch_bounds__(512, 1)
scan_kernel(const int* __restrict__ pmask,   // bool as int32 (B,S,L)
            float* __restrict__ out) {
    extern __shared__ float sm[];
    float* h       = sm;                 // K*D   32KB
    float* kv      = h + Kn * D;         // K*D   32KB
    float* e_sh    = kv + Kn * D;        // D
    float* ew_sh   = e_sh + D;           // D
    float* ek_sh   = ew_sh + D;          // K
    float* gate_sh = ek_sh + Kn;         // K
    float* rs_sh   = gate_sh + Kn;       // K
    int*   smask   = (int*)(rs_sh + Kn); // S

    const int b     = blockIdx.x;
    const int t     = threadIdx.x;
    const int c     = t & 255;
    const int kbase = (t >> 8) * 16;
    const int w     = t >> 5;
    const int lane  = t & 31;

    for (int i = t; i < Kn * D; i += 512) {
        h[i]  = 0.f;
        kv[i] = g_keysV[(size_t)b * Kn * D + i];
    }
    if (t < Sn) smask[t] = pmask[((size_t)b * Sn + t) * Ln];
    __syncthreads();

    const unsigned long long* Upk = (const unsigned long long*)g_Upk;

    for (int s = 0; s < Sn; ++s) {
        if (smask[s] == 0) continue;

        if (t < 256)      e_sh[t]  = g_enc [((size_t)b * Sn + s) * D + t];
        else              ew_sh[c] = g_encW[((size_t)b * Sn + s) * D + c];
        if (t < Kn)       ek_sh[t] = g_eK  [((size_t)b * Sn + s) * Kn + t];
        __syncthreads();

        // gate[k] = sigmoid(e·h[k] + eK[k]) ; warp w handles rows 2w, 2w+1
#pragma unroll
        for (int r = 0; r < 2; ++r) {
            int k = 2 * w + r;
            float p = 0.f;
#pragma unroll
            for (int j = 0; j < 8; ++j) {
                int col = lane + 32 * j;
                p = fmaf(e_sh[col], h[k * D + col], p);
            }
#pragma unroll
            for (int o = 16; o > 0; o >>= 1) p += __shfl_xor_sync(0xffffffffu, p, o);
            if (lane == 0) gate_sh[k] = 1.f / (1.f + expf(-(p + ek_sh[k])));
        }
        __syncthreads();

        // acc2[k] = packed even/odd-d partial sums of (h @ U)[kbase+k, c]
        unsigned long long acc2[16];
#pragma unroll
        for (int k = 0; k < 16; ++k) acc2[k] = 0ull;

        for (int d0 = 0; d0 < D; d0 += 8) {
            unsigned long long u0 = __ldg(Upk + (size_t)((d0 >> 1) + 0) * D + c);
            unsigned long long u1 = __ldg(Upk + (size_t)((d0 >> 1) + 1) * D + c);
            unsigned long long u2 = __ldg(Upk + (size_t)((d0 >> 1) + 2) * D + c);
            unsigned long long u3 = __ldg(Upk + (size_t)((d0 >> 1) + 3) * D + c);
#pragma unroll
            for (int k = 0; k < 16; ++k) {
                const ulonglong2* hp =
                    (const ulonglong2*)&h[(kbase + k) * D + d0];
                ulonglong2 h01 = hp[0];   // d0..d0+3  (two f32 pairs)
                ulonglong2 h23 = hp[1];   // d0+4..d0+7
                FMA_F32X2(acc2[k], h01.x, u0, acc2[k]);
                FMA_F32X2(acc2[k], h01.y, u1, acc2[k]);
                FMA_F32X2(acc2[k], h23.x, u2, acc2[k]);
                FMA_F32X2(acc2[k], h23.y, u3, acc2[k]);
            }
        }

        // upd = h + gate * relu(hU + keysV + eW)
        float ew = ew_sh[c];
        float upd[16];
#pragma unroll
        for (int k = 0; k < 16; ++k) {
            float2 a = *(float2*)&acc2[k];
            float hu = a.x + a.y;
            float ht = fmaxf(hu + kv[(kbase + k) * D + c] + ew, 0.f);
            upd[k] = fmaf(gate_sh[kbase + k], ht, h[(kbase + k) * D + c]);
        }
        __syncthreads();   // all reads of old h complete
#pragma unroll
        for (int k = 0; k < 16; ++k) h[(kbase + k) * D + c] = upd[k];
        __syncthreads();

        // row norms
#pragma unroll
        for (int r = 0; r < 2; ++r) {
            int k = 2 * w + r;
            float p = 0.f;
#pragma unroll
            for (int j = 0; j < 8; ++j) {
                float v = h[k * D + lane + 32 * j];
                p = fmaf(v, v, p);
            }
#pragma unroll
            for (int o = 16; o > 0; o >>= 1) p += __shfl_xor_sync(0xffffffffu, p, o);
            if (lane == 0) rs_sh[k] = rsqrtf(fmaxf(p, 1e-12f));
        }
        __syncthreads();
#pragma unroll
        for (int k = 0; k < 16; ++k)
            h[(kbase + k) * D + c] = upd[k] * rs_sh[kbase + k];
        __syncthreads();
    }

    for (int i = t; i < Kn * D; i += 512) out[(size_t)b * Kn * D + i] = h[i];
}

// ---------------------------------------------------------------------------
extern "C" void kernel_launch(void* const* d_in, const int* in_sizes, int n_in,
                              void* d_out, int out_size) {
    const int*   prgrph = (const int*)d_in[0];
    const int*   pmask  = (const int*)d_in[1];
    const float* keys   = (const float*)d_in[2];
    const float* emb    = (const float*)d_in[3];
    const float* U      = (const float*)d_in[4];
    const float* V      = (const float*)d_in[5];
    const float* W      = (const float*)d_in[6];
    float*       out    = (float*)d_out;

    const int scan_smem =
        (2 * Kn * D + 2 * D + 3 * Kn) * (int)sizeof(float) + Sn * (int)sizeof(int);
    cudaFuncSetAttribute(scan_kernel, cudaFuncAttributeMaxDynamicSharedMemorySize,
                         scan_smem);

    gather_kernel<<<Bn * Sn, 256>>>(prgrph, emb);
    packU_kernel<<<D / 2, 256>>>(U);
    eK_kernel<<<Bn * Sn, 256>>>(keys);
    gemm_encW_kernel<<<(Bn * Sn) / 32, 256>>>(W);
    gemm_keysV_kernel<<<(Bn * Kn) / 32, 256>>>(keys, V);
    scan_kernel<<<Bn, 512, scan_smem>>>(pmask, out);
}

// round 5
// speedup vs baseline: 2.0458x; 1.1850x over previous
#include <cuda_runtime.h>
#include <cuda_bf16.h>
#include <math.h>

#define VOCAB 50000
#define D 256
#define Bn 128
#define Sn 64
#define Ln 32
#define Kn 32

// Scratch (device globals: allocation-free rule)
__device__ float  g_enc [Bn * Sn * D];          // enc_sents   (B,S,D)
__device__ float  g_encW[Bn * Sn * D];          // enc_sents@W (B,S,D)
__device__ float  g_keysV[Bn * Kn * D];         // keys@V      (B,K,D)
__device__ float  g_eK  [Bn * Sn * Kn];         // enc·keys    (B,S,K)
__device__ float2 g_Upk [(D / 2) * D];          // U packed: [p][c] = (U[2p][c], U[2p+1][c])

#define FMA_F32X2(d_, a_, b_, c_) \
    asm("fma.rn.f32x2 %0, %1, %2, %3;" : "=l"(d_) : "l"(a_), "l"(b_), "l"(c_))

// ---------------------------------------------------------------------------
// enc_sents[b,s,d] = sum_l emb[prgrph[b,s,l], d]
// ---------------------------------------------------------------------------
__global__ void gather_kernel(const int* __restrict__ prgrph,
                              const float* __restrict__ emb) {
    __shared__ int sidx[Ln];
    int bs = blockIdx.x;
    int t  = threadIdx.x;
    if (t < Ln) sidx[t] = prgrph[(size_t)bs * Ln + t];
    __syncthreads();
    float acc = 0.f;
#pragma unroll
    for (int l = 0; l < Ln; ++l) acc += __ldg(emb + (size_t)sidx[l] * D + t);
    g_enc[(size_t)bs * D + t] = acc;
}

// ---------------------------------------------------------------------------
// Pack U rows into float2 pairs along d: g_Upk[p*D + c] = (U[2p][c], U[2p+1][c])
// ---------------------------------------------------------------------------
__global__ void packU_kernel(const float* __restrict__ U) {
    int p = blockIdx.x;        // 0..127
    int c = threadIdx.x;       // 0..255
    g_Upk[p * D + c] = make_float2(U[(2 * p) * D + c], U[(2 * p + 1) * D + c]);
}

// ---------------------------------------------------------------------------
// eK[b,s,k] = sum_d enc[b,s,d] * keys[b,k,d]       grid = B*S, 256 threads
// ---------------------------------------------------------------------------
__global__ void eK_kernel(const float* __restrict__ keys) {
    __shared__ float e_sh[D];
    int bs   = blockIdx.x;
    int b    = bs / Sn;
    int t    = threadIdx.x;
    int w    = t >> 5, lane = t & 31;
    e_sh[t]  = g_enc[(size_t)bs * D + t];
    __syncthreads();
#pragma unroll
    for (int r = 0; r < 4; ++r) {
        int k = w * 4 + r;
        const float* kr = keys + ((size_t)b * Kn + k) * D;
        float p = 0.f;
#pragma unroll
        for (int j = 0; j < 8; ++j) {
            int c = lane + 32 * j;
            p = fmaf(e_sh[c], __ldg(kr + c), p);
        }
#pragma unroll
        for (int o = 16; o > 0; o >>= 1) p += __shfl_xor_sync(0xffffffffu, p, o);
        if (lane == 0) g_eK[(size_t)bs * Kn + k] = p;
    }
}

// ---------------------------------------------------------------------------
// 32-row GEMM tile: C[32,D] = A[32,D] @ Bm[D,D]
// ---------------------------------------------------------------------------
__device__ __forceinline__ void gemm32_body(const float* __restrict__ Ab,
                                            const float* __restrict__ Bm,
                                            float* __restrict__ Cb) {
    __shared__ float a_sh[32 * D];
    int t = threadIdx.x;
    for (int i = t; i < 32 * D; i += 256) a_sh[i] = Ab[i];
    __syncthreads();

    float acc[32];
#pragma unroll
    for (int k = 0; k < 32; ++k) acc[k] = 0.f;

    for (int d0 = 0; d0 < D; d0 += 8) {
        float u[8];
#pragma unroll
        for (int i = 0; i < 8; ++i) u[i] = __ldg(Bm + (size_t)(d0 + i) * D + t);
#pragma unroll
        for (int k = 0; k < 32; ++k) {
            float4 h1 = *(const float4*)&a_sh[k * D + d0];
            float4 h2 = *(const float4*)&a_sh[k * D + d0 + 4];
            acc[k] = fmaf(h1.x, u[0], acc[k]); acc[k] = fmaf(h1.y, u[1], acc[k]);
            acc[k] = fmaf(h1.z, u[2], acc[k]); acc[k] = fmaf(h1.w, u[3], acc[k]);
            acc[k] = fmaf(h2.x, u[4], acc[k]); acc[k] = fmaf(h2.y, u[5], acc[k]);
            acc[k] = fmaf(h2.z, u[6], acc[k]); acc[k] = fmaf(h2.w, u[7], acc[k]);
        }
    }
#pragma unroll
    for (int k = 0; k < 32; ++k) Cb[k * D + t] = acc[k];
}

__global__ void gemm_encW_kernel(const float* __restrict__ W) {
    size_t off = (size_t)blockIdx.x * 32 * D;
    gemm32_body(g_enc + off, W, g_encW + off);
}
__global__ void gemm_keysV_kernel(const float* __restrict__ keys,
                                  const float* __restrict__ V) {
    size_t off = (size_t)blockIdx.x * 32 * D;
    gemm32_body(keys + off, V, g_keysV + off);
}

// ---------------------------------------------------------------------------
// The scan. One CTA per batch; 512 threads.
// Thread t: column group cg = t&127 -> cols (cg, cg+128);
//           row group   rg = t>>7  -> rows rg*8 .. rg*8+7.
// h kept UNNORMALIZED in smem; per-row scale rs_sh[k] folded into gate/epilogue.
// ---------------------------------------------------------------------------
__global__ void __launch_bounds__(512, 1)
scan_kernel(const int* __restrict__ pmask,   // bool as int32 (B,S,L)
            float* __restrict__ out) {
    __shared__ float h[Kn * D];          // 32 KB, unnormalized state
    __shared__ float e_sh[D];
    __shared__ float ew_sh[D];
    __shared__ float ek_sh[Kn];
    __shared__ float gate_sh[Kn];
    __shared__ float rs_sh[Kn];
    __shared__ int   smask[Sn];

    const int b    = blockIdx.x;
    const int t    = threadIdx.x;
    const int cg   = t & 127;
    const int kb   = (t >> 7) * 8;       // row base (0,8,16,24)
    const int c0   = cg;
    const int c1   = cg + 128;
    const int w    = t >> 5;
    const int lane = t & 31;

    // per-thread persistent registers
    float hrA[8], hrB[8];                // this thread's h_raw values
    float kvA[8], kvB[8];                // keysV (loop-invariant)
#pragma unroll
    for (int r = 0; r < 8; ++r) {
        hrA[r] = 0.f; hrB[r] = 0.f;
        kvA[r] = g_keysV[((size_t)b * Kn + kb + r) * D + c0];
        kvB[r] = g_keysV[((size_t)b * Kn + kb + r) * D + c1];
    }
    for (int i = t; i < Kn * D; i += 512) h[i] = 0.f;
    if (t < Sn) smask[t] = pmask[((size_t)b * Sn + t) * Ln];
    if (t < Kn) rs_sh[t] = 1.f;
    __syncthreads();

    const unsigned long long* Upk = (const unsigned long long*)g_Upk;

    for (int s = 0; s < Sn; ++s) {
        if (smask[s] == 0) continue;

        if (t < 256) e_sh[t]        = g_enc [((size_t)b * Sn + s) * D + t];
        else         ew_sh[t - 256] = g_encW[((size_t)b * Sn + s) * D + (t - 256)];
        if (t < Kn)  ek_sh[t]       = g_eK  [((size_t)b * Sn + s) * Kn + t];
        __syncthreads();                              // [L]

        // gate[k] = sigmoid(rs[k] * (e . h_raw[k]) + eK[k]); warp w: rows 2w,2w+1
#pragma unroll
        for (int r = 0; r < 2; ++r) {
            int k = 2 * w + r;
            float p = 0.f;
#pragma unroll
            for (int j = 0; j < 8; ++j) {
                int col = lane + 32 * j;
                p = fmaf(e_sh[col], h[k * D + col], p);
            }
#pragma unroll
            for (int o = 16; o > 0; o >>= 1) p += __shfl_xor_sync(0xffffffffu, p, o);
            if (lane == 0)
                gate_sh[k] = 1.f / (1.f + expf(-(fmaf(rs_sh[k], p, ek_sh[k]))));
        }

        // GEMM: acc = h_raw @ Upk for 8 rows x 2 columns
        unsigned long long accA[8], accB[8];
#pragma unroll
        for (int r = 0; r < 8; ++r) { accA[r] = 0ull; accB[r] = 0ull; }

        for (int d0 = 0; d0 < D; d0 += 8) {
            const size_t p = (size_t)(d0 >> 1);
            unsigned long long ua0 = __ldg(Upk + (p + 0) * D + c0);
            unsigned long long ub0 = __ldg(Upk + (p + 0) * D + c1);
            unsigned long long ua1 = __ldg(Upk + (p + 1) * D + c0);
            unsigned long long ub1 = __ldg(Upk + (p + 1) * D + c1);
            unsigned long long ua2 = __ldg(Upk + (p + 2) * D + c0);
            unsigned long long ub2 = __ldg(Upk + (p + 2) * D + c1);
            unsigned long long ua3 = __ldg(Upk + (p + 3) * D + c0);
            unsigned long long ub3 = __ldg(Upk + (p + 3) * D + c1);
#pragma unroll
            for (int r = 0; r < 8; ++r) {
                const ulonglong2* hp = (const ulonglong2*)&h[(kb + r) * D + d0];
                ulonglong2 h01 = hp[0];
                ulonglong2 h23 = hp[1];
                FMA_F32X2(accA[r], h01.x, ua0, accA[r]);
                FMA_F32X2(accB[r], h01.x, ub0, accB[r]);
                FMA_F32X2(accA[r], h01.y, ua1, accA[r]);
                FMA_F32X2(accB[r], h01.y, ub1, accB[r]);
                FMA_F32X2(accA[r], h23.x, ua2, accA[r]);
                FMA_F32X2(accB[r], h23.x, ub2, accB[r]);
                FMA_F32X2(accA[r], h23.y, ua3, accA[r]);
                FMA_F32X2(accB[r], h23.y, ub3, accB[r]);
            }
        }
        __syncthreads();            // [A] gate_sh visible; all h reads complete

        // upd = rs*h_raw + gate * relu(rs*hU + keysV + eW); store unnormalized
        const float ewA = ew_sh[c0];
        const float ewB = ew_sh[c1];
#pragma unroll
        for (int r = 0; r < 8; ++r) {
            int   k  = kb + r;
            float rs = rs_sh[k];
            float g  = gate_sh[k];
            float2 aA = *(float2*)&accA[r];
            float2 aB = *(float2*)&accB[r];
            float htA = fmaxf(fmaf(rs, aA.x + aA.y, kvA[r] + ewA), 0.f);
            float htB = fmaxf(fmaf(rs, aB.x + aB.y, kvB[r] + ewB), 0.f);
            hrA[r] = fmaf(g, htA, rs * hrA[r]);
            hrB[r] = fmaf(g, htB, rs * hrB[r]);
            h[k * D + c0] = hrA[r];
            h[k * D + c1] = hrB[r];
        }
        __syncthreads();            // [B] new h visible

        // row norms -> rs_sh (no rescale pass; folded into next step)
#pragma unroll
        for (int r = 0; r < 2; ++r) {
            int k = 2 * w + r;
            float p = 0.f;
#pragma unroll
            for (int j = 0; j < 8; ++j) {
                float v = h[k * D + lane + 32 * j];
                p = fmaf(v, v, p);
            }
#pragma unroll
            for (int o = 16; o > 0; o >>= 1) p += __shfl_xor_sync(0xffffffffu, p, o);
            if (lane == 0) rs_sh[k] = rsqrtf(fmaxf(p, 1e-12f));
        }
        __syncthreads();            // [C] rs visible for next step / output
    }

#pragma unroll
    for (int r = 0; r < 8; ++r) {
        int k = kb + r;
        out[((size_t)b * Kn + k) * D + c0] = hrA[r] * rs_sh[k];
        out[((size_t)b * Kn + k) * D + c1] = hrB[r] * rs_sh[k];
    }
}

// ---------------------------------------------------------------------------
extern "C" void kernel_launch(void* const* d_in, const int* in_sizes, int n_in,
                              void* d_out, int out_size) {
    const int*   prgrph = (const int*)d_in[0];
    const int*   pmask  = (const int*)d_in[1];
    const float* keys   = (const float*)d_in[2];
    const float* emb    = (const float*)d_in[3];
    const float* U      = (const float*)d_in[4];
    const float* V      = (const float*)d_in[5];
    const float* W      = (const float*)d_in[6];
    float*       out    = (float*)d_out;

    gather_kernel<<<Bn * Sn, 256>>>(prgrph, emb);
    packU_kernel<<<D / 2, 256>>>(U);
    eK_kernel<<<Bn * Sn, 256>>>(keys);
    gemm_encW_kernel<<<(Bn * Sn) / 32, 256>>>(W);
    gemm_keysV_kernel<<<(Bn * Kn) / 32, 256>>>(keys, V);
    scan_kernel<<<Bn, 512>>>(pmask, out);
}

// round 6
// speedup vs baseline: 2.2493x; 1.0995x over previous
#include <cuda_runtime.h>
#include <cuda_bf16.h>
#include <cuda_pipeline.h>
#include <math.h>

#define VOCAB 50000
#define D 256
#define Bn 128
#define Sn 64
#define Ln 32
#define Kn 32

// Scratch (device globals: allocation-free rule)
__device__ float  g_enc [Bn * Sn * D];          // enc_sents   (B,S,D)
__device__ float  g_encW[Bn * Sn * D];          // enc_sents@W (B,S,D)
__device__ float  g_keysV[Bn * Kn * D];         // keys@V      (B,K,D)
__device__ float  g_eK  [Bn * Sn * Kn];         // enc·keys    (B,S,K)
__device__ float2 g_Upk [(D / 2) * D];          // U packed: [p][c] = (U[2p][c], U[2p+1][c])

#define FMA_F32X2(d_, a_, b_, c_) \
    asm("fma.rn.f32x2 %0, %1, %2, %3;" : "=l"(d_) : "l"(a_), "l"(b_), "l"(c_))

// ---------------------------------------------------------------------------
// Fused: enc_sents[b,s,d] = sum_l emb[prgrph[b,s,l], d]
//        eK[b,s,k]        = sum_d enc[b,s,d] * keys[b,k,d]
// grid = B*S, 256 threads
// ---------------------------------------------------------------------------
__global__ void gather_eK_kernel(const int* __restrict__ prgrph,
                                 const float* __restrict__ emb,
                                 const float* __restrict__ keys) {
    __shared__ int   sidx[Ln];
    __shared__ float e_sh[D];
    int bs = blockIdx.x;
    int b  = bs / Sn;
    int t  = threadIdx.x;
    int w  = t >> 5, lane = t & 31;
    if (t < Ln) sidx[t] = prgrph[(size_t)bs * Ln + t];
    __syncthreads();
    float acc = 0.f;
#pragma unroll
    for (int l = 0; l < Ln; ++l) acc += __ldg(emb + (size_t)sidx[l] * D + t);
    g_enc[(size_t)bs * D + t] = acc;
    e_sh[t] = acc;
    __syncthreads();
#pragma unroll
    for (int r = 0; r < 4; ++r) {
        int k = w * 4 + r;
        const float* kr = keys + ((size_t)b * Kn + k) * D;
        float p = 0.f;
#pragma unroll
        for (int j = 0; j < 8; ++j) {
            int c = lane + 32 * j;
            p = fmaf(e_sh[c], __ldg(kr + c), p);
        }
#pragma unroll
        for (int o = 16; o > 0; o >>= 1) p += __shfl_xor_sync(0xffffffffu, p, o);
        if (lane == 0) g_eK[(size_t)bs * Kn + k] = p;
    }
}

// ---------------------------------------------------------------------------
// Pack U rows into float2 pairs along d: g_Upk[p*D + c] = (U[2p][c], U[2p+1][c])
// ---------------------------------------------------------------------------
__global__ void packU_kernel(const float* __restrict__ U) {
    int p = blockIdx.x;
    int c = threadIdx.x;
    g_Upk[p * D + c] = make_float2(U[(2 * p) * D + c], U[(2 * p + 1) * D + c]);
}

// ---------------------------------------------------------------------------
// 32-row GEMM tile: C[32,D] = A[32,D] @ Bm[D,D]
// ---------------------------------------------------------------------------
__device__ __forceinline__ void gemm32_body(const float* __restrict__ Ab,
                                            const float* __restrict__ Bm,
                                            float* __restrict__ Cb) {
    __shared__ float a_sh[32 * D];
    int t = threadIdx.x;
    for (int i = t; i < 32 * D; i += 256) a_sh[i] = Ab[i];
    __syncthreads();

    float acc[32];
#pragma unroll
    for (int k = 0; k < 32; ++k) acc[k] = 0.f;

    for (int d0 = 0; d0 < D; d0 += 8) {
        float u[8];
#pragma unroll
        for (int i = 0; i < 8; ++i) u[i] = __ldg(Bm + (size_t)(d0 + i) * D + t);
#pragma unroll
        for (int k = 0; k < 32; ++k) {
            float4 h1 = *(const float4*)&a_sh[k * D + d0];
            float4 h2 = *(const float4*)&a_sh[k * D + d0 + 4];
            acc[k] = fmaf(h1.x, u[0], acc[k]); acc[k] = fmaf(h1.y, u[1], acc[k]);
            acc[k] = fmaf(h1.z, u[2], acc[k]); acc[k] = fmaf(h1.w, u[3], acc[k]);
            acc[k] = fmaf(h2.x, u[4], acc[k]); acc[k] = fmaf(h2.y, u[5], acc[k]);
            acc[k] = fmaf(h2.z, u[6], acc[k]); acc[k] = fmaf(h2.w, u[7], acc[k]);
        }
    }
#pragma unroll
    for (int k = 0; k < 32; ++k) Cb[k * D + t] = acc[k];
}

// encW (blocks 0..255) + keysV (blocks 256..383) in one launch
__global__ void gemm_pre_kernel(const float* __restrict__ keys,
                                const float* __restrict__ V,
                                const float* __restrict__ W) {
    int blk = blockIdx.x;
    if (blk < 256) {
        size_t off = (size_t)blk * 32 * D;
        gemm32_body(g_enc + off, W, g_encW + off);
    } else {
        size_t off = (size_t)(blk - 256) * 32 * D;
        gemm32_body(keys + off, V, g_keysV + off);
    }
}

// ---------------------------------------------------------------------------
// The scan. One CTA per batch; 512 threads.
// Thread t: cols (cg, cg+128) where cg=t&127; rows kb..kb+7 where kb=(t>>7)*8.
// U staged through smem via cp.async double buffering (4 chunks of 64KB/step).
// h kept UNNORMALIZED in smem; per-row scale rs_sh folded into gate/epilogue.
// ---------------------------------------------------------------------------
#define CHUNK_PAIRS 32                 // packed rows per chunk (= 64 d values)
#define NCHUNK      4                  // 128 packed rows total
#define CHUNK_BYTES (CHUNK_PAIRS * D * 8)   // 64 KB

__global__ void __launch_bounds__(512, 1)
scan_kernel(const int* __restrict__ pmask,   // bool as int32 (B,S,L)
            float* __restrict__ out) {
    extern __shared__ char smraw[];
    float* h     = (float*)smraw;                         // 32 KB
    char*  ubuf0 = smraw + Kn * D * 4;                    // 64 KB
    char*  ubuf1 = ubuf0 + CHUNK_BYTES;                   // 64 KB
    float* ew_sh = (float*)(ubuf1 + CHUNK_BYTES);         // 1 KB
    float* gate_sh = ew_sh + D;                           // 128 B
    float* rs_sh   = gate_sh + Kn;                        // 128 B
    int*   smask   = (int*)(rs_sh + Kn);                  // 256 B

    const int b    = blockIdx.x;
    const int t    = threadIdx.x;
    const int cg   = t & 127;
    const int kb   = (t >> 7) * 8;
    const int c0   = cg;
    const int c1   = cg + 128;
    const int w    = t >> 5;
    const int lane = t & 31;

    float hrA[8], hrB[8], kvA[8], kvB[8];
#pragma unroll
    for (int r = 0; r < 8; ++r) {
        hrA[r] = 0.f; hrB[r] = 0.f;
        kvA[r] = g_keysV[((size_t)b * Kn + kb + r) * D + c0];
        kvB[r] = g_keysV[((size_t)b * Kn + kb + r) * D + c1];
    }
    for (int i = t; i < Kn * D; i += 512) h[i] = 0.f;
    if (t < Sn) smask[t] = pmask[((size_t)b * Sn + t) * Ln];
    if (t < Kn) rs_sh[t] = 1.f;
    __syncthreads();

    const char* Usrc = (const char*)g_Upk;

    for (int s = 0; s < Sn; ++s) {
        if (smask[s] == 0) continue;

        // prefetch chunk 0 of U
#pragma unroll
        for (int i = 0; i < 8; ++i) {
            size_t g = (size_t)t * 16 + (size_t)i * 512 * 16;
            __pipeline_memcpy_async(ubuf0 + g, Usrc + g, 16);
        }
        __pipeline_commit();

        // per-step vectors (no barrier needed before use; see sync points below)
        if (t < 256) ew_sh[t] = g_encW[((size_t)b * Sn + s) * D + t];

        // gate[k] = sigmoid(rs[k]*(e . h_raw[k]) + eK[k]); warp w: rows 2w,2w+1
        {
            const float* ep = g_enc + ((size_t)b * Sn + s) * D;
            float ev[8];
#pragma unroll
            for (int j = 0; j < 8; ++j) ev[j] = __ldg(ep + lane + 32 * j);
#pragma unroll
            for (int r = 0; r < 2; ++r) {
                int k = 2 * w + r;
                float p = 0.f;
#pragma unroll
                for (int j = 0; j < 8; ++j)
                    p = fmaf(ev[j], h[k * D + lane + 32 * j], p);
#pragma unroll
                for (int o = 16; o > 0; o >>= 1)
                    p += __shfl_xor_sync(0xffffffffu, p, o);
                if (lane == 0) {
                    float ek = __ldg(g_eK + ((size_t)b * Sn + s) * Kn + k);
                    gate_sh[k] = 1.f / (1.f + expf(-(fmaf(rs_sh[k], p, ek))));
                }
            }
        }

        // GEMM with double-buffered U chunks
        unsigned long long accA[8], accB[8];
#pragma unroll
        for (int r = 0; r < 8; ++r) { accA[r] = 0ull; accB[r] = 0ull; }

#pragma unroll
        for (int ch = 0; ch < NCHUNK; ++ch) {
            __pipeline_wait_prior(0);
            __syncthreads();   // chunk ch resident in buf[ch&1]; prev compute done
            if (ch < NCHUNK - 1) {
                char* dst = (ch & 1) ? ubuf0 : ubuf1;
                const char* src = Usrc + (size_t)(ch + 1) * CHUNK_BYTES;
#pragma unroll
                for (int i = 0; i < 8; ++i) {
                    size_t g = (size_t)t * 16 + (size_t)i * 512 * 16;
                    __pipeline_memcpy_async(dst + g, src + g, 16);
                }
                __pipeline_commit();
            }
            const unsigned long long* usm =
                (const unsigned long long*)((ch & 1) ? ubuf1 : ubuf0);
            const int dbase = ch * (CHUNK_PAIRS * 2);

            for (int d0l = 0; d0l < CHUNK_PAIRS * 2; d0l += 8) {
                const int pl = d0l >> 1;
                unsigned long long ua0 = usm[(pl + 0) * D + c0];
                unsigned long long ub0 = usm[(pl + 0) * D + c1];
                unsigned long long ua1 = usm[(pl + 1) * D + c0];
                unsigned long long ub1 = usm[(pl + 1) * D + c1];
                unsigned long long ua2 = usm[(pl + 2) * D + c0];
                unsigned long long ub2 = usm[(pl + 2) * D + c1];
                unsigned long long ua3 = usm[(pl + 3) * D + c0];
                unsigned long long ub3 = usm[(pl + 3) * D + c1];
#pragma unroll
                for (int r = 0; r < 8; ++r) {
                    const ulonglong2* hp =
                        (const ulonglong2*)&h[(kb + r) * D + dbase + d0l];
                    ulonglong2 h01 = hp[0];
                    ulonglong2 h23 = hp[1];
                    FMA_F32X2(accA[r], h01.x, ua0, accA[r]);
                    FMA_F32X2(accB[r], h01.x, ub0, accB[r]);
                    FMA_F32X2(accA[r], h01.y, ua1, accA[r]);
                    FMA_F32X2(accB[r], h01.y, ub1, accB[r]);
                    FMA_F32X2(accA[r], h23.x, ua2, accA[r]);
                    FMA_F32X2(accB[r], h23.x, ub2, accB[r]);
                    FMA_F32X2(accA[r], h23.y, ua3, accA[r]);
                    FMA_F32X2(accB[r], h23.y, ub3, accB[r]);
                }
            }
        }
        __syncthreads();   // [A] all h reads (gate + GEMM) complete

        // upd = rs*h_raw + gate * relu(rs*hU + keysV + eW); store unnormalized
        const float ewA = ew_sh[c0];
        const float ewB = ew_sh[c1];
#pragma unroll
        for (int r = 0; r < 8; ++r) {
            int   k  = kb + r;
            float rs = rs_sh[k];
            float g  = gate_sh[k];
            float2 aA = *(float2*)&accA[r];
            float2 aB = *(float2*)&accB[r];
            float htA = fmaxf(fmaf(rs, aA.x + aA.y, kvA[r] + ewA), 0.f);
            float htB = fmaxf(fmaf(rs, aB.x + aB.y, kvB[r] + ewB), 0.f);
            hrA[r] = fmaf(g, htA, rs * hrA[r]);
            hrB[r] = fmaf(g, htB, rs * hrB[r]);
            h[k * D + c0] = hrA[r];
            h[k * D + c1] = hrB[r];
        }
        __syncthreads();   // [B] new h visible

        // row norms -> rs_sh (folded into next step / output)
#pragma unroll
        for (int r = 0; r < 2; ++r) {
            int k = 2 * w + r;
            float p = 0.f;
#pragma unroll
            for (int j = 0; j < 8; ++j) {
                float v = h[k * D + lane + 32 * j];
                p = fmaf(v, v, p);
            }
#pragma unroll
            for (int o = 16; o > 0; o >>= 1) p += __shfl_xor_sync(0xffffffffu, p, o);
            if (lane == 0) rs_sh[k] = rsqrtf(fmaxf(p, 1e-12f));
        }
        __syncthreads();   // [C]
    }

#pragma unroll
    for (int r = 0; r < 8; ++r) {
        int k = kb + r;
        out[((size_t)b * Kn + k) * D + c0] = hrA[r] * rs_sh[k];
        out[((size_t)b * Kn + k) * D + c1] = hrB[r] * rs_sh[k];
    }
}

// ---------------------------------------------------------------------------
extern "C" void kernel_launch(void* const* d_in, const int* in_sizes, int n_in,
                              void* d_out, int out_size) {
    const int*   prgrph = (const int*)d_in[0];
    const int*   pmask  = (const int*)d_in[1];
    const float* keys   = (const float*)d_in[2];
    const float* emb    = (const float*)d_in[3];
    const float* U      = (const float*)d_in[4];
    const float* V      = (const float*)d_in[5];
    const float* W      = (const float*)d_in[6];
    float*       out    = (float*)d_out;

    const int scan_smem = Kn * D * 4 + 2 * CHUNK_BYTES +
                          (D + 2 * Kn) * 4 + Sn * 4 + 256;  // ~166.5 KB
    cudaFuncSetAttribute(scan_kernel, cudaFuncAttributeMaxDynamicSharedMemorySize,
                         scan_smem);

    gather_eK_kernel<<<Bn * Sn, 256>>>(prgrph, emb, keys);
    packU_kernel<<<D / 2, 256>>>(U);
    gemm_pre_kernel<<<384, 256>>>(keys, V, W);
    scan_kernel<<<Bn, 512, scan_smem>>>(pmask, out);
}